// round 7
// baseline (speedup 1.0000x reference)
#include <cuda_runtime.h>
#include <math.h>

// Problem constants
#define BATCH 64
#define NSEQ  256
#define MSEQ  256
#define DDIM  512
#define BIGF  1e8f
#define BIGD  1e8

// Scratch (device globals — no runtime allocation allowed)
// Z: [hx;hy] @ [Wm|Wg] + [bm|bg]  -> 32768 rows x 1024 cols
__device__ float g_Z[32768u * 1024u];
// V in diagonal-major layout, DOUBLE precision: per batch 513 diagonals x 257
__device__ double g_V[(size_t)BATCH * 513 * 257];

// ---------------------------------------------------------------------------
// K1: projection GEMM.  Z[r, 0:512]   = X[r] @ Wm + bm
//                       Z[r, 512:1024]= X[r] @ Wg + bg
// X = concat(hx (16384x512), hy (16384x512)) row-major.
// Classic 128x128x8 fp32 tile, 256 threads, 8x8 per thread.
// ---------------------------------------------------------------------------
__global__ __launch_bounds__(256) void k_proj(
    const float* __restrict__ hx, const float* __restrict__ hy,
    const float* __restrict__ Wm, const float* __restrict__ bm,
    const float* __restrict__ Wg, const float* __restrict__ bg)
{
    __shared__ float As[8][128];
    __shared__ float Bs[8][128];

    const int tid = threadIdx.x;
    const int bx  = blockIdx.x;      // 0..7 : output-column tiles of 128
    const int by  = blockIdx.y;      // 0..255 : row tiles of 128
    const int row0 = by * 128;

    const float* X    = (row0 < 16384) ? (hx + (size_t)row0 * 512)
                                       : (hy + (size_t)(row0 - 16384) * 512);
    const float* W    = (bx < 4) ? Wm : Wg;
    const float* bias = (bx < 4) ? bm : bg;
    const int wc0     = (bx < 4) ? bx * 128 : (bx - 4) * 128;

    const int a_row = tid >> 1;          // 0..127
    const int a_col = (tid & 1) * 4;     // 0 or 4
    const int b_row = tid >> 5;          // 0..7
    const int b_col = (tid & 31) * 4;    // 0..124

    const int ty = tid >> 4;             // 0..15
    const int tx = tid & 15;             // 0..15

    float acc[8][8];
#pragma unroll
    for (int i = 0; i < 8; i++)
#pragma unroll
        for (int j = 0; j < 8; j++) acc[i][j] = 0.f;

    for (int k0 = 0; k0 < 512; k0 += 8) {
        float4 av = *(const float4*)(X + (size_t)a_row * 512 + k0 + a_col);
        float4 bv = *(const float4*)(W + (size_t)(k0 + b_row) * 512 + wc0 + b_col);
        __syncthreads();
        As[a_col + 0][a_row] = av.x;
        As[a_col + 1][a_row] = av.y;
        As[a_col + 2][a_row] = av.z;
        As[a_col + 3][a_row] = av.w;
        *(float4*)&Bs[b_row][b_col] = bv;
        __syncthreads();
#pragma unroll
        for (int kk = 0; kk < 8; kk++) {
            float ar[8], br[8];
#pragma unroll
            for (int i = 0; i < 8; i++) ar[i] = As[kk][ty * 8 + i];
#pragma unroll
            for (int j = 0; j < 8; j++) br[j] = Bs[kk][tx * 8 + j];
#pragma unroll
            for (int i = 0; i < 8; i++)
#pragma unroll
                for (int j = 0; j < 8; j++) acc[i][j] += ar[i] * br[j];
        }
    }

#pragma unroll
    for (int j = 0; j < 8; j++) {
        float bb = bias[wc0 + tx * 8 + j];
#pragma unroll
        for (int i = 0; i < 8; i++) {
            g_Z[(size_t)(row0 + ty * 8 + i) * 1024 + bx * 128 + tx * 8 + j] =
                acc[i][j] + bb;
        }
    }
}

// ---------------------------------------------------------------------------
// K2: per-batch NT GEMM + activation.
//  which==0: theta[b] = softplus(zx[b] @ zy[b]^T)
//  which==1: A[b]     = log_sigmoid(gx[b] @ gy[b]^T)
// ---------------------------------------------------------------------------
__global__ __launch_bounds__(256) void k_pair(float* __restrict__ theta,
                                              float* __restrict__ Aout)
{
    __shared__ float As[8][128];
    __shared__ float Bs[8][128];

    const int tid   = threadIdx.x;
    const int bz    = blockIdx.z;
    const int batch = bz >> 1;
    const int which = bz & 1;
    const int ro    = blockIdx.y * 128;
    const int co    = blockIdx.x * 128;

    const float* Xb = g_Z + (size_t)(batch * 256) * 1024 + (which ? 512 : 0);
    const float* Yb = g_Z + (size_t)(16384 + batch * 256) * 1024 + (which ? 512 : 0);

    const int a_row = tid >> 1;
    const int a_col = (tid & 1) * 4;
    const int ty = tid >> 4;
    const int tx = tid & 15;

    float acc[8][8];
#pragma unroll
    for (int i = 0; i < 8; i++)
#pragma unroll
        for (int j = 0; j < 8; j++) acc[i][j] = 0.f;

    for (int k0 = 0; k0 < 512; k0 += 8) {
        float4 av = *(const float4*)(Xb + (size_t)(ro + a_row) * 1024 + k0 + a_col);
        float4 bv = *(const float4*)(Yb + (size_t)(co + a_row) * 1024 + k0 + a_col);
        __syncthreads();
        As[a_col + 0][a_row] = av.x;
        As[a_col + 1][a_row] = av.y;
        As[a_col + 2][a_row] = av.z;
        As[a_col + 3][a_row] = av.w;
        Bs[a_col + 0][a_row] = bv.x;
        Bs[a_col + 1][a_row] = bv.y;
        Bs[a_col + 2][a_row] = bv.z;
        Bs[a_col + 3][a_row] = bv.w;
        __syncthreads();
#pragma unroll
        for (int kk = 0; kk < 8; kk++) {
            float ar[8], br[8];
#pragma unroll
            for (int i = 0; i < 8; i++) ar[i] = As[kk][ty * 8 + i];
#pragma unroll
            for (int j = 0; j < 8; j++) br[j] = Bs[kk][tx * 8 + j];
#pragma unroll
            for (int i = 0; i < 8; i++)
#pragma unroll
                for (int j = 0; j < 8; j++) acc[i][j] += ar[i] * br[j];
        }
    }

    float* O = which ? Aout : theta;
    const size_t base = (size_t)batch * NSEQ * MSEQ;
#pragma unroll
    for (int i = 0; i < 8; i++) {
#pragma unroll
        for (int j = 0; j < 8; j++) {
            float x  = acc[i][j];
            float l1 = log1pf(expf(-fabsf(x)));
            float v  = which ? (fminf(x, 0.f) - l1)    // log_sigmoid
                             : (fmaxf(x, 0.f) + l1);   // softplus
            O[base + (size_t)(ro + ty * 8 + i) * MSEQ + (co + tx * 8 + j)] = v;
        }
    }
}

// ---------------------------------------------------------------------------
// K3: smooth Needleman-Wunsch forward + backward, one block/batch.
// V carried in DOUBLE precision: V grows to ~8000, where float ulp (~5e-4)
// injected per-cell rounding noise into the backward weight exponents and
// blew the 1e-3 budget. With double V the weight exponents
//     e_up   = A + V[i-1,j]   - (V[i,j] - theta)
//     e_diag =     V[i-1,j-1] - (V[i,j] - theta)
//     e_left = A + V[i,j-1]   - (V[i,j] - theta)
// are formed as double differences (error ~1e-12) before one float __expf
// (args <= 0, underflow->0 is the correct limit).
// aln[i-1,j-1] = E[i,j];  E[N,M] = 1.
// ---------------------------------------------------------------------------
__global__ __launch_bounds__(256) void k_nw(const float* __restrict__ theta,
                                            const float* __restrict__ Aarr,
                                            float* __restrict__ aln)
{
    const int b = blockIdx.x;
    const int t = threadIdx.x;
    const float* TH = theta + (size_t)b * NSEQ * MSEQ;
    const float* AA = Aarr  + (size_t)b * NSEQ * MSEQ;
    float*       AL = aln   + (size_t)b * NSEQ * MSEQ;
    double*      V  = g_V   + (size_t)b * 513 * 257;

    __shared__ double f0[257], f1[257], f2[257];      // forward V diagonals
    __shared__ double Va_[257], Vb_[257], Vc_[257];   // backward V diagonals
    __shared__ float Eb_[258], E1_[258], E2_[258];
    __shared__ float cu[258], cl[258], cd[258];

    const int i = t + 1;   // row index 1..256

    // -------- forward --------
    double *d2 = f0, *d1 = f1, *d0 = f2;
    for (int m = t; m < 257; m += 256) {
        d2[m] = (m == 0) ? 0.0 : -BIGD;   // diagonal k=0
        d1[m] = -BIGD;                    // diagonal k=1
        V[0 * 257 + m] = d2[m];
        V[1 * 257 + m] = -BIGD;
    }
    __syncthreads();

    for (int k = 2; k <= 512; k++) {
        const int j = k - i;
        double nv = -BIGD;
        if (j >= 1 && j <= MSEQ) {
            float  a  = AA[(i - 1) * MSEQ + (j - 1)];
            float  th = TH[(i - 1) * MSEQ + (j - 1)];
            double c0 = (double)a + d1[i - 1];   // A + V[i-1,j]
            double c1 = d2[i - 1];               // V[i-1,j-1]
            double c2 = (double)a + d1[i];       // A + V[i,j-1]
            double m1 = fmax(c0, fmax(c1, c2));
            // shifted args <= 0 and small in magnitude (or -1e8 -> exp=0)
            float s = __expf((float)(c0 - m1)) + __expf((float)(c1 - m1)) +
                      __expf((float)(c2 - m1));
            nv = (double)th + m1 + (double)logf(s);
        }
        d0[i] = nv;
        V[(size_t)k * 257 + i] = nv;
        if (t == 0) { d0[0] = -BIGD; V[(size_t)k * 257] = -BIGD; }
        __syncthreads();
        double* tmp = d2; d2 = d1; d1 = d0; d0 = tmp;
    }

    // -------- backward --------
    float  *Eb = Eb_, *E1 = E1_, *E2 = E2_;
    double *Va = Va_, *Vb = Vb_, *Vc = Vc_;
    for (int m = t; m < 258; m += 256) {
        Eb[m] = (m == 256) ? 1.f : 0.f;   // E at (N,M) on diagonal k=512
        E1[m] = 0.f; E2[m] = 0.f;
        cu[m] = 0.f; cl[m] = 0.f; cd[m] = 0.f;
    }
    for (int m = t; m < 257; m += 256) {
        Va[m] = V[(size_t)512 * 257 + m];
        Vb[m] = V[(size_t)511 * 257 + m];
        Vc[m] = V[(size_t)510 * 257 + m];
    }
    __syncthreads();

    for (int k = 512; k >= 2; k--) {
        const int j = k - i;
        float E = Eb[i];
        float wu = 0.f, wl = 0.f, wd = 0.f;
        if (j >= 1 && j <= MSEQ) {
            float a  = AA[(i - 1) * MSEQ + (j - 1)];
            float th = TH[(i - 1) * MSEQ + (j - 1)];
            AL[(i - 1) * MSEQ + (j - 1)] = E;
            double S = Va[i] - (double)th;               // lse value at (i,j)
            wu = E * __expf((float)((double)a + Vb[i - 1] - S)); // -> (i-1, j)
            wd = E * __expf((float)(Vc[i - 1] - S));             // -> (i-1, j-1)
            wl = E * __expf((float)((double)a + Vb[i] - S));     // -> (i,   j-1)
        }
        cu[i] = wu; cl[i] = wl; cd[i] = wd;
        __syncthreads();

        // accumulate into parent diagonals (slot m on diag k-1 gets up from
        // child i=m+1 and left from child i=m; diag k-2 slot m gets diag
        // contribution from child i=m+1)
        for (int m = t; m < 257; m += 256) {
            E1[m] += cu[m + 1] + cl[m];
            E2[m] += cd[m + 1];
        }
        // recycle Eb as fresh accumulator, old Va as buffer for diag k-3
        for (int m = t; m < 258; m += 256) Eb[m] = 0.f;
        if (k >= 3) {
            for (int m = t; m < 257; m += 256)
                Va[m] = V[(size_t)(k - 3) * 257 + m];
        }
        __syncthreads();

        float*  tE = Eb; Eb = E1; E1 = E2; E2 = tE;
        double* tV = Va; Va = Vb; Vb = Vc; Vc = tV;
    }
}

// ---------------------------------------------------------------------------
// Launch. Inputs (metadata order = setup_inputs order):
//   0: hx (64,256,512) f32   1: hy (64,256,512) f32
//   2: Wm (512,512) f32      3: bm (512) f32
//   4: Wg (512,512) f32      5: bg (512) f32
// Output: concat(aln, theta, A), each (64,256,256) f32.
// ---------------------------------------------------------------------------
extern "C" void kernel_launch(void* const* d_in, const int* in_sizes, int n_in,
                              void* d_out, int out_size)
{
    const float* hx = (const float*)d_in[0];
    const float* hy = (const float*)d_in[1];
    const float* Wm = (const float*)d_in[2];
    const float* bm = (const float*)d_in[3];
    const float* Wg = (const float*)d_in[4];
    const float* bg = (const float*)d_in[5];

    float* out = (float*)d_out;
    size_t third = (size_t)out_size / 3;       // 64*256*256
    float* aln_p   = out;
    float* theta_p = out + third;
    float* A_p     = out + 2 * third;

    k_proj<<<dim3(8, 256), 256>>>(hx, hy, Wm, bm, Wg, bg);
    k_pair<<<dim3(2, 2, 2 * BATCH), 256>>>(theta_p, A_p);
    k_nw<<<BATCH, 256>>>(theta_p, A_p, aln_p);
}

// round 9
// speedup vs baseline: 1.0244x; 1.0244x over previous
#include <cuda_runtime.h>
#include <math.h>

// Problem constants
#define BATCH 64
#define NSEQ  256
#define MSEQ  256
#define DDIM  512
#define BIGD  1e8

// Scratch (device globals — no runtime allocation allowed)
// Z: [hx;hy] @ [Wm|Wg] + [bm|bg]  -> 32768 rows x 1024 cols
__device__ float g_Z[32768u * 1024u];
// V in diagonal-major layout, DOUBLE precision: per batch 513 diagonals x 257
__device__ double g_V[(size_t)BATCH * 513 * 257];

// ---------------------------------------------------------------------------
// K1: projection GEMM.  Z[r, 0:512]   = X[r] @ Wm + bm
//                       Z[r, 512:1024]= X[r] @ Wg + bg
// 128x128x8 fp32 tile, 256 threads, 8x8/thread, 2-stage smem double buffer
// (one bar.sync per K-step, global loads issued one compute-tile ahead).
// ---------------------------------------------------------------------------
__global__ __launch_bounds__(256) void k_proj(
    const float* __restrict__ hx, const float* __restrict__ hy,
    const float* __restrict__ Wm, const float* __restrict__ bm,
    const float* __restrict__ Wg, const float* __restrict__ bg)
{
    __shared__ float As[2][8][128];
    __shared__ float Bs[2][8][128];

    const int tid = threadIdx.x;
    const int bx  = blockIdx.x;      // 0..7 : output-column tiles of 128
    const int by  = blockIdx.y;      // 0..255 : row tiles of 128
    const int row0 = by * 128;

    const float* X    = (row0 < 16384) ? (hx + (size_t)row0 * 512)
                                       : (hy + (size_t)(row0 - 16384) * 512);
    const float* W    = (bx < 4) ? Wm : Wg;
    const float* bias = (bx < 4) ? bm : bg;
    const int wc0     = (bx < 4) ? bx * 128 : (bx - 4) * 128;

    const int a_row = tid >> 1;          // 0..127
    const int a_col = (tid & 1) * 4;     // 0 or 4
    const int b_row = tid >> 5;          // 0..7
    const int b_col = (tid & 31) * 4;    // 0..124

    const int ty = tid >> 4;             // 0..15
    const int tx = tid & 15;             // 0..15

    float acc[8][8];
#pragma unroll
    for (int i = 0; i < 8; i++)
#pragma unroll
        for (int j = 0; j < 8; j++) acc[i][j] = 0.f;

    // preload stage 0
    float4 av = *(const float4*)(X + (size_t)a_row * 512 + a_col);
    float4 bv = *(const float4*)(W + (size_t)b_row * 512 + wc0 + b_col);
    As[0][a_col + 0][a_row] = av.x;
    As[0][a_col + 1][a_row] = av.y;
    As[0][a_col + 2][a_row] = av.z;
    As[0][a_col + 3][a_row] = av.w;
    *(float4*)&Bs[0][b_row][b_col] = bv;
    __syncthreads();

    int s = 0;
    for (int k0 = 0; k0 < 512; k0 += 8) {
        if (k0 + 8 < 512) {
            av = *(const float4*)(X + (size_t)a_row * 512 + (k0 + 8) + a_col);
            bv = *(const float4*)(W + (size_t)(k0 + 8 + b_row) * 512 + wc0 + b_col);
        }
#pragma unroll
        for (int kk = 0; kk < 8; kk++) {
            float ar[8], br[8];
#pragma unroll
            for (int i = 0; i < 8; i++) ar[i] = As[s][kk][ty * 8 + i];
#pragma unroll
            for (int j = 0; j < 8; j++) br[j] = Bs[s][kk][tx * 8 + j];
#pragma unroll
            for (int i = 0; i < 8; i++)
#pragma unroll
                for (int j = 0; j < 8; j++) acc[i][j] += ar[i] * br[j];
        }
        if (k0 + 8 < 512) {
            As[s ^ 1][a_col + 0][a_row] = av.x;
            As[s ^ 1][a_col + 1][a_row] = av.y;
            As[s ^ 1][a_col + 2][a_row] = av.z;
            As[s ^ 1][a_col + 3][a_row] = av.w;
            *(float4*)&Bs[s ^ 1][b_row][b_col] = bv;
            __syncthreads();
            s ^= 1;
        }
    }

#pragma unroll
    for (int j = 0; j < 8; j++) {
        float bb = bias[wc0 + tx * 8 + j];
#pragma unroll
        for (int i = 0; i < 8; i++) {
            g_Z[(size_t)(row0 + ty * 8 + i) * 1024 + bx * 128 + tx * 8 + j] =
                acc[i][j] + bb;
        }
    }
}

// ---------------------------------------------------------------------------
// K2: per-batch NT GEMM + activation, same double-buffer scheme.
//  which==0: theta[b] = softplus(zx[b] @ zy[b]^T)
//  which==1: A[b]     = log_sigmoid(gx[b] @ gy[b]^T)
// ---------------------------------------------------------------------------
__global__ __launch_bounds__(256) void k_pair(float* __restrict__ theta,
                                              float* __restrict__ Aout)
{
    __shared__ float As[2][8][128];
    __shared__ float Bs[2][8][128];

    const int tid   = threadIdx.x;
    const int bz    = blockIdx.z;
    const int batch = bz >> 1;
    const int which = bz & 1;
    const int ro    = blockIdx.y * 128;
    const int co    = blockIdx.x * 128;

    const float* Xb = g_Z + (size_t)(batch * 256) * 1024 + (which ? 512 : 0);
    const float* Yb = g_Z + (size_t)(16384 + batch * 256) * 1024 + (which ? 512 : 0);

    const int a_row = tid >> 1;
    const int a_col = (tid & 1) * 4;
    const int ty = tid >> 4;
    const int tx = tid & 15;

    float acc[8][8];
#pragma unroll
    for (int i = 0; i < 8; i++)
#pragma unroll
        for (int j = 0; j < 8; j++) acc[i][j] = 0.f;

    float4 av = *(const float4*)(Xb + (size_t)(ro + a_row) * 1024 + a_col);
    float4 bv = *(const float4*)(Yb + (size_t)(co + a_row) * 1024 + a_col);
    As[0][a_col + 0][a_row] = av.x;
    As[0][a_col + 1][a_row] = av.y;
    As[0][a_col + 2][a_row] = av.z;
    As[0][a_col + 3][a_row] = av.w;
    Bs[0][a_col + 0][a_row] = bv.x;
    Bs[0][a_col + 1][a_row] = bv.y;
    Bs[0][a_col + 2][a_row] = bv.z;
    Bs[0][a_col + 3][a_row] = bv.w;
    __syncthreads();

    int s = 0;
    for (int k0 = 0; k0 < 512; k0 += 8) {
        if (k0 + 8 < 512) {
            av = *(const float4*)(Xb + (size_t)(ro + a_row) * 1024 + (k0 + 8) + a_col);
            bv = *(const float4*)(Yb + (size_t)(co + a_row) * 1024 + (k0 + 8) + a_col);
        }
#pragma unroll
        for (int kk = 0; kk < 8; kk++) {
            float ar[8], br[8];
#pragma unroll
            for (int i = 0; i < 8; i++) ar[i] = As[s][kk][ty * 8 + i];
#pragma unroll
            for (int j = 0; j < 8; j++) br[j] = Bs[s][kk][tx * 8 + j];
#pragma unroll
            for (int i = 0; i < 8; i++)
#pragma unroll
                for (int j = 0; j < 8; j++) acc[i][j] += ar[i] * br[j];
        }
        if (k0 + 8 < 512) {
            As[s ^ 1][a_col + 0][a_row] = av.x;
            As[s ^ 1][a_col + 1][a_row] = av.y;
            As[s ^ 1][a_col + 2][a_row] = av.z;
            As[s ^ 1][a_col + 3][a_row] = av.w;
            Bs[s ^ 1][a_col + 0][a_row] = bv.x;
            Bs[s ^ 1][a_col + 1][a_row] = bv.y;
            Bs[s ^ 1][a_col + 2][a_row] = bv.z;
            Bs[s ^ 1][a_col + 3][a_row] = bv.w;
            __syncthreads();
            s ^= 1;
        }
    }

    float* O = which ? Aout : theta;
    const size_t base = (size_t)batch * NSEQ * MSEQ;
#pragma unroll
    for (int i = 0; i < 8; i++) {
#pragma unroll
        for (int j = 0; j < 8; j++) {
            float x  = acc[i][j];
            float l1 = log1pf(expf(-fabsf(x)));
            float v  = which ? (fminf(x, 0.f) - l1)    // log_sigmoid
                             : (fmaxf(x, 0.f) + l1);   // softplus
            O[base + (size_t)(ro + ty * 8 + i) * MSEQ + (co + tx * 8 + j)] = v;
        }
    }
}

// float4 component select without local-array spill
__device__ __forceinline__ float f4sel(const float4& v, int sel) {
    float lo = (sel == 0) ? v.x : v.y;
    float hi = (sel == 2) ? v.z : v.w;
    return (sel < 2) ? lo : hi;
}

// ---------------------------------------------------------------------------
// K3: smooth Needleman-Wunsch forward + backward, one block/batch.
// V carried in double (float ulp at |V|~8000 blew the 1e-3 budget in R6).
// Each thread i owns matrix row i-1; its theta/A accesses are contiguous in
// j, so both passes stream them through float4 register chunks with
// one-chunk-ahead prefetch (was: 32-wavefront stride-1KB LDG per step on the
// serial critical path). aln stores are buffered to float4. Backward
// prefetches V[k-3] a full iteration early.
// ---------------------------------------------------------------------------
__global__ __launch_bounds__(256) void k_nw(const float* __restrict__ theta,
                                            const float* __restrict__ Aarr,
                                            float* __restrict__ aln)
{
    const int b = blockIdx.x;
    const int t = threadIdx.x;
    const float* TH = theta + (size_t)b * NSEQ * MSEQ;
    const float* AA = Aarr  + (size_t)b * NSEQ * MSEQ;
    float*       AL = aln   + (size_t)b * NSEQ * MSEQ;
    double*      V  = g_V   + (size_t)b * 513 * 257;

    __shared__ double f0[257], f1[257], f2[257];      // forward V diagonals
    __shared__ double Va_[257], Vb_[257], Vc_[257];   // backward V diagonals
    __shared__ float Eb_[258], E1_[258], E2_[258];
    __shared__ float cu[258], cl[258], cd[258];

    const int i = t + 1;   // matrix row index 1..256
    const float* rowT = TH + (size_t)(i - 1) * MSEQ;
    const float* rowA = AA + (size_t)(i - 1) * MSEQ;
    float*       rowL = AL + (size_t)(i - 1) * MSEQ;

    // -------- forward --------
    double *d2 = f0, *d1 = f1, *d0 = f2;
    for (int m = t; m < 257; m += 256) {
        d2[m] = (m == 0) ? 0.0 : -BIGD;   // diagonal k=0
        d1[m] = -BIGD;                    // diagonal k=1
        V[0 * 257 + m] = d2[m];
        V[1 * 257 + m] = -BIGD;
    }
    float4 tC, tN, aC, aN;
    tN = *(const float4*)rowT;            // chunk 0 prefetch
    aN = *(const float4*)rowA;
    __syncthreads();

    for (int k = 2; k <= 512; k++) {
        const int jm1 = k - i - 1;        // 0-based column this thread touches
        double nv = -BIGD;
        if (jm1 >= 0 && jm1 < MSEQ) {
            const int sel = jm1 & 3;
            if (sel == 0) {
                tC = tN; aC = aN;
                if (jm1 + 4 < MSEQ) {
                    tN = *(const float4*)(rowT + jm1 + 4);
                    aN = *(const float4*)(rowA + jm1 + 4);
                }
            }
            float th = f4sel(tC, sel);
            float a  = f4sel(aC, sel);
            double c0 = (double)a + d1[i - 1];   // A + V[i-1,j]
            double c1 = d2[i - 1];               // V[i-1,j-1]
            double c2 = (double)a + d1[i];       // A + V[i,j-1]
            double m1 = fmax(c0, fmax(c1, c2));
            float s = __expf((float)(c0 - m1)) + __expf((float)(c1 - m1)) +
                      __expf((float)(c2 - m1));
            nv = (double)th + m1 + (double)__logf(s);
        }
        d0[i] = nv;
        V[(size_t)k * 257 + i] = nv;
        if (t == 0) { d0[0] = -BIGD; V[(size_t)k * 257] = -BIGD; }
        __syncthreads();
        double* tmp = d2; d2 = d1; d1 = d0; d0 = tmp;
    }

    // -------- backward --------
    float  *Eb = Eb_, *E1 = E1_, *E2 = E2_;
    double *Va = Va_, *Vb = Vb_, *Vc = Vc_;
    for (int m = t; m < 258; m += 256) {
        Eb[m] = (m == 256) ? 1.f : 0.f;   // E at (N,M) on diagonal k=512
        E1[m] = 0.f; E2[m] = 0.f;
        cu[m] = 0.f; cl[m] = 0.f; cd[m] = 0.f;
    }
    for (int m = t; m < 257; m += 256) {
        Va[m] = V[(size_t)512 * 257 + m];
        Vb[m] = V[(size_t)511 * 257 + m];
        Vc[m] = V[(size_t)510 * 257 + m];
    }
    float4 alB = make_float4(0.f, 0.f, 0.f, 0.f);
    __syncthreads();

    for (int k = 512; k >= 2; k--) {
        const int jm1 = k - i - 1;
        // prefetch V diag k-3 into registers (consumed after first sync)
        double vp0 = 0.0, vp1 = 0.0;
        if (k >= 3) {
            vp0 = V[(size_t)(k - 3) * 257 + t];
            if (t == 0) vp1 = V[(size_t)(k - 3) * 257 + 256];
        }
        float E = Eb[i];
        float wu = 0.f, wl = 0.f, wd = 0.f;
        if (jm1 >= 0 && jm1 < MSEQ) {
            const int sel = jm1 & 3;
            if (sel == 3) {                       // entering a new chunk (descending)
                if (jm1 == MSEQ - 1) {            // first activation
                    tC = *(const float4*)(rowT + jm1 - 3);
                    aC = *(const float4*)(rowA + jm1 - 3);
                } else { tC = tN; aC = aN; }
                if (jm1 - 7 >= 0) {
                    tN = *(const float4*)(rowT + jm1 - 7);
                    aN = *(const float4*)(rowA + jm1 - 7);
                }
            }
            float th = f4sel(tC, sel);
            float a  = f4sel(aC, sel);
            if      (sel == 3) alB.w = E;
            else if (sel == 2) alB.z = E;
            else if (sel == 1) alB.y = E;
            else               alB.x = E;
            if (sel == 0) *(float4*)(rowL + jm1) = alB;   // chunk complete
            double S = Va[i] - (double)th;                // lse value at (i,j)
            wu = E * __expf((float)((double)a + Vb[i - 1] - S)); // -> (i-1, j)
            wd = E * __expf((float)(Vc[i - 1] - S));             // -> (i-1, j-1)
            wl = E * __expf((float)((double)a + Vb[i] - S));     // -> (i,   j-1)
        }
        cu[i] = wu; cl[i] = wl; cd[i] = wd;
        __syncthreads();

        // accumulate into parent diagonals
        for (int m = t; m < 257; m += 256) {
            E1[m] += cu[m + 1] + cl[m];
            E2[m] += cd[m + 1];
        }
        for (int m = t; m < 258; m += 256) Eb[m] = 0.f;
        if (k >= 3) {
            Va[t] = vp0;                    // old Va rotates to become Vc
            if (t == 0) Va[256] = vp1;
        }
        __syncthreads();

        float*  tE = Eb; Eb = E1; E1 = E2; E2 = tE;
        double* tV = Va; Va = Vb; Vb = Vc; Vc = tV;
    }
}

// ---------------------------------------------------------------------------
// Launch. Inputs: hx, hy, Wm, bm, Wg, bg (f32).
// Output: concat(aln, theta, A), each (64,256,256) f32.
// ---------------------------------------------------------------------------
extern "C" void kernel_launch(void* const* d_in, const int* in_sizes, int n_in,
                              void* d_out, int out_size)
{
    const float* hx = (const float*)d_in[0];
    const float* hy = (const float*)d_in[1];
    const float* Wm = (const float*)d_in[2];
    const float* bm = (const float*)d_in[3];
    const float* Wg = (const float*)d_in[4];
    const float* bg = (const float*)d_in[5];

    float* out = (float*)d_out;
    size_t third = (size_t)out_size / 3;       // 64*256*256
    float* aln_p   = out;
    float* theta_p = out + third;
    float* A_p     = out + 2 * third;

    k_proj<<<dim3(8, 256), 256>>>(hx, hy, Wm, bm, Wg, bg);
    k_pair<<<dim3(2, 2, 2 * BATCH), 256>>>(theta_p, A_p);
    k_nw<<<BATCH, 256>>>(theta_p, A_p, aln_p);
}

// round 11
// speedup vs baseline: 1.2991x; 1.2682x over previous
#include <cuda_runtime.h>
#include <math.h>

// Problem constants
#define BATCH 64
#define NSEQ  256
#define MSEQ  256
#define DDIM  512
#define BIGF  1e8f

// Scratch (device globals — no runtime allocation allowed)
// Z: [hx;hy] @ [Wm|Wg] + [bm|bg]  -> 32768 rows x 1024 cols
__device__ float g_Z[32768u * 1024u];
// Per-cell backward log-weights (u-L, w-L), diag-major: 513 diagonals x 257
__device__ float2 g_W[(size_t)BATCH * 513 * 257];

// ---- Blackwell packed-fp32 helpers (fma.rn.f32x2: 1 issue slot = 2 FMAs) ----
__device__ __forceinline__ unsigned long long pk2(float lo, float hi) {
    unsigned long long r;
    asm("mov.b64 %0, {%1, %2};" : "=l"(r) : "f"(lo), "f"(hi));
    return r;
}
__device__ __forceinline__ void upk2(unsigned long long v, float& lo, float& hi) {
    asm("mov.b64 {%0, %1}, %2;" : "=f"(lo), "=f"(hi) : "l"(v));
}
__device__ __forceinline__ unsigned long long ffma2(unsigned long long a,
        unsigned long long b, unsigned long long c) {
    unsigned long long d;
    asm("fma.rn.f32x2 %0, %1, %2, %3;" : "=l"(d) : "l"(a), "l"(b), "l"(c));
    return d;
}

// ---------------------------------------------------------------------------
// K1: projection GEMM.  Z[r, 0:512]   = X[r] @ Wm + bm
//                       Z[r, 512:1024]= X[r] @ Wg + bg
// 128x128x8 tile, 256 threads, 8x8/thread, double-buffered smem,
// f32x2 packed FMA mainloop (halves issue-slot demand of the FFMA stream).
// ---------------------------------------------------------------------------
__global__ __launch_bounds__(256) void k_proj(
    const float* __restrict__ hx, const float* __restrict__ hy,
    const float* __restrict__ Wm, const float* __restrict__ bm,
    const float* __restrict__ Wg, const float* __restrict__ bg)
{
    __shared__ float As[2][8][128];
    __shared__ float Bs[2][8][128];

    const int tid = threadIdx.x;
    const int bx  = blockIdx.x;      // 0..7 : output-column tiles of 128
    const int by  = blockIdx.y;      // 0..255 : row tiles of 128
    const int row0 = by * 128;

    const float* X    = (row0 < 16384) ? (hx + (size_t)row0 * 512)
                                       : (hy + (size_t)(row0 - 16384) * 512);
    const float* W    = (bx < 4) ? Wm : Wg;
    const float* bias = (bx < 4) ? bm : bg;
    const int wc0     = (bx < 4) ? bx * 128 : (bx - 4) * 128;

    const int a_row = tid >> 1;          // 0..127
    const int a_col = (tid & 1) * 4;     // 0 or 4
    const int b_row = tid >> 5;          // 0..7
    const int b_col = (tid & 31) * 4;    // 0..124

    const int ty = tid >> 4;             // 0..15
    const int tx = tid & 15;             // 0..15

    unsigned long long acc2[8][4];       // 8 rows x 4 col-pairs of f32x2
#pragma unroll
    for (int i = 0; i < 8; i++)
#pragma unroll
        for (int p = 0; p < 4; p++) acc2[i][p] = 0ull;

    // preload stage 0
    float4 av = *(const float4*)(X + (size_t)a_row * 512 + a_col);
    float4 bv = *(const float4*)(W + (size_t)b_row * 512 + wc0 + b_col);
    As[0][a_col + 0][a_row] = av.x;
    As[0][a_col + 1][a_row] = av.y;
    As[0][a_col + 2][a_row] = av.z;
    As[0][a_col + 3][a_row] = av.w;
    *(float4*)&Bs[0][b_row][b_col] = bv;
    __syncthreads();

    int s = 0;
    for (int k0 = 0; k0 < 512; k0 += 8) {
        if (k0 + 8 < 512) {
            av = *(const float4*)(X + (size_t)a_row * 512 + (k0 + 8) + a_col);
            bv = *(const float4*)(W + (size_t)(k0 + 8 + b_row) * 512 + wc0 + b_col);
        }
#pragma unroll
        for (int kk = 0; kk < 8; kk++) {
            const float4* ap = (const float4*)&As[s][kk][ty * 8];
            float4 a0 = ap[0], a1 = ap[1];
            const float4* bp = (const float4*)&Bs[s][kk][tx * 8];
            float4 b0 = bp[0], b1 = bp[1];
            unsigned long long bb0 = pk2(b0.x, b0.y), bb1 = pk2(b0.z, b0.w);
            unsigned long long bb2 = pk2(b1.x, b1.y), bb3 = pk2(b1.z, b1.w);
            float ar[8] = {a0.x, a0.y, a0.z, a0.w, a1.x, a1.y, a1.z, a1.w};
#pragma unroll
            for (int i = 0; i < 8; i++) {
                unsigned long long aa = pk2(ar[i], ar[i]);
                acc2[i][0] = ffma2(aa, bb0, acc2[i][0]);
                acc2[i][1] = ffma2(aa, bb1, acc2[i][1]);
                acc2[i][2] = ffma2(aa, bb2, acc2[i][2]);
                acc2[i][3] = ffma2(aa, bb3, acc2[i][3]);
            }
        }
        if (k0 + 8 < 512) {
            As[s ^ 1][a_col + 0][a_row] = av.x;
            As[s ^ 1][a_col + 1][a_row] = av.y;
            As[s ^ 1][a_col + 2][a_row] = av.z;
            As[s ^ 1][a_col + 3][a_row] = av.w;
            *(float4*)&Bs[s ^ 1][b_row][b_col] = bv;
            __syncthreads();
            s ^= 1;
        }
    }

#pragma unroll
    for (int i = 0; i < 8; i++) {
        const int row = row0 + ty * 8 + i;
#pragma unroll
        for (int p = 0; p < 4; p++) {
            float lo, hi;
            upk2(acc2[i][p], lo, hi);
            const int c = tx * 8 + 2 * p;
            g_Z[(size_t)row * 1024 + bx * 128 + c]     = lo + bias[wc0 + c];
            g_Z[(size_t)row * 1024 + bx * 128 + c + 1] = hi + bias[wc0 + c + 1];
        }
    }
}

// ---------------------------------------------------------------------------
// K2: per-batch NT GEMM + activation, same f32x2 scheme.
//  which==0: theta[b] = softplus(zx[b] @ zy[b]^T)
//  which==1: A[b]     = log_sigmoid(gx[b] @ gy[b]^T)
// ---------------------------------------------------------------------------
__global__ __launch_bounds__(256) void k_pair(float* __restrict__ theta,
                                              float* __restrict__ Aout)
{
    __shared__ float As[2][8][128];
    __shared__ float Bs[2][8][128];

    const int tid   = threadIdx.x;
    const int bz    = blockIdx.z;
    const int batch = bz >> 1;
    const int which = bz & 1;
    const int ro    = blockIdx.y * 128;
    const int co    = blockIdx.x * 128;

    const float* Xb = g_Z + (size_t)(batch * 256) * 1024 + (which ? 512 : 0);
    const float* Yb = g_Z + (size_t)(16384 + batch * 256) * 1024 + (which ? 512 : 0);

    const int a_row = tid >> 1;
    const int a_col = (tid & 1) * 4;
    const int ty = tid >> 4;
    const int tx = tid & 15;

    unsigned long long acc2[8][4];
#pragma unroll
    for (int i = 0; i < 8; i++)
#pragma unroll
        for (int p = 0; p < 4; p++) acc2[i][p] = 0ull;

    float4 av = *(const float4*)(Xb + (size_t)(ro + a_row) * 1024 + a_col);
    float4 bv = *(const float4*)(Yb + (size_t)(co + a_row) * 1024 + a_col);
    As[0][a_col + 0][a_row] = av.x;
    As[0][a_col + 1][a_row] = av.y;
    As[0][a_col + 2][a_row] = av.z;
    As[0][a_col + 3][a_row] = av.w;
    Bs[0][a_col + 0][a_row] = bv.x;
    Bs[0][a_col + 1][a_row] = bv.y;
    Bs[0][a_col + 2][a_row] = bv.z;
    Bs[0][a_col + 3][a_row] = bv.w;
    __syncthreads();

    int s = 0;
    for (int k0 = 0; k0 < 512; k0 += 8) {
        if (k0 + 8 < 512) {
            av = *(const float4*)(Xb + (size_t)(ro + a_row) * 1024 + (k0 + 8) + a_col);
            bv = *(const float4*)(Yb + (size_t)(co + a_row) * 1024 + (k0 + 8) + a_col);
        }
#pragma unroll
        for (int kk = 0; kk < 8; kk++) {
            const float4* ap = (const float4*)&As[s][kk][ty * 8];
            float4 a0 = ap[0], a1 = ap[1];
            const float4* bp = (const float4*)&Bs[s][kk][tx * 8];
            float4 b0 = bp[0], b1 = bp[1];
            unsigned long long bb0 = pk2(b0.x, b0.y), bb1 = pk2(b0.z, b0.w);
            unsigned long long bb2 = pk2(b1.x, b1.y), bb3 = pk2(b1.z, b1.w);
            float ar[8] = {a0.x, a0.y, a0.z, a0.w, a1.x, a1.y, a1.z, a1.w};
#pragma unroll
            for (int i = 0; i < 8; i++) {
                unsigned long long aa = pk2(ar[i], ar[i]);
                acc2[i][0] = ffma2(aa, bb0, acc2[i][0]);
                acc2[i][1] = ffma2(aa, bb1, acc2[i][1]);
                acc2[i][2] = ffma2(aa, bb2, acc2[i][2]);
                acc2[i][3] = ffma2(aa, bb3, acc2[i][3]);
            }
        }
        if (k0 + 8 < 512) {
            As[s ^ 1][a_col + 0][a_row] = av.x;
            As[s ^ 1][a_col + 1][a_row] = av.y;
            As[s ^ 1][a_col + 2][a_row] = av.z;
            As[s ^ 1][a_col + 3][a_row] = av.w;
            Bs[s ^ 1][a_col + 0][a_row] = bv.x;
            Bs[s ^ 1][a_col + 1][a_row] = bv.y;
            Bs[s ^ 1][a_col + 2][a_row] = bv.z;
            Bs[s ^ 1][a_col + 3][a_row] = bv.w;
            __syncthreads();
            s ^= 1;
        }
    }

    float* O = which ? Aout : theta;
    const size_t base = (size_t)batch * NSEQ * MSEQ;
#pragma unroll
    for (int i = 0; i < 8; i++) {
        const int row = ro + ty * 8 + i;
#pragma unroll
        for (int p = 0; p < 4; p++) {
            float xv[2];
            upk2(acc2[i][p], xv[0], xv[1]);
#pragma unroll
            for (int h = 0; h < 2; h++) {
                float x  = xv[h];
                float l1 = log1pf(expf(-fabsf(x)));
                float v  = which ? (fminf(x, 0.f) - l1)    // log_sigmoid
                                 : (fmaxf(x, 0.f) + l1);   // softplus
                O[base + (size_t)row * MSEQ + (co + tx * 8 + 2 * p + h)] = v;
            }
        }
    }
}

// float4 component select without local-array spill
__device__ __forceinline__ float f4sel(const float4& v, int sel) {
    float lo = (sel == 0) ? v.x : v.y;
    float hi = (sel == 2) ? v.z : v.w;
    return (sel < 2) ? lo : hi;
}

// ---------------------------------------------------------------------------
// K3: smooth NW forward + backward, one block/batch — ALL-FLOAT difference
// recurrence (eliminates the fp64 dependency chain that bound this kernel).
// Propagate R(i,j)=V(i,j)-V(i,j-1), C(i,j)=V(i,j)-V(i-1,j) instead of V:
//   u = A + R(i-1,j);  w = A + C(i,j-1);  L = lse(u, w, 0)
//   Rnew = theta + A + L - w;  Cnew = theta + A + L - u
// All values O(30) except +-1e8 boundary sentinels. Audited: every consumer
// of a BIG-riding value has it as the DOMINANT lse candidate, so L equals it
// bit-for-bit and L-w / L-u cancel exactly — sentinel rounding (ulp(1e8)=8)
// never leaks into interior (i>=2, j>=2) quantities.
// Backward softmax log-weights are (u-L, w-L, -L); forward stores
// float2(u-L, w-L) per cell, backward computes wu=E*exp(eu), wl=E*exp(el),
// wd = E - wu - wl (exact simplex) — no theta/A/V loads in backward at all.
// ---------------------------------------------------------------------------
__global__ __launch_bounds__(256) void k_nw(const float* __restrict__ theta,
                                            const float* __restrict__ Aarr,
                                            float* __restrict__ aln)
{
    const int b = blockIdx.x;
    const int t = threadIdx.x;
    const float* TH = theta + (size_t)b * NSEQ * MSEQ;
    const float* AA = Aarr  + (size_t)b * NSEQ * MSEQ;
    float*       AL = aln   + (size_t)b * NSEQ * MSEQ;
    float2*      Wd = g_W   + (size_t)b * 513 * 257;

    __shared__ float Rb[2][258], Cb[2][258];          // difference diagonals
    __shared__ float Eb_[258], E1_[258], E2_[258];
    __shared__ float cu[258], cl[258], cd[258];

    const int i = t + 1;   // matrix row index 1..256
    const float* rowT = TH + (size_t)(i - 1) * MSEQ;
    const float* rowA = AA + (size_t)(i - 1) * MSEQ;
    float*       rowL = AL + (size_t)(i - 1) * MSEQ;

    // -------- forward --------
    for (int m = t; m < 258; m += 256) {
        Rb[0][m] = 0.f; Cb[0][m] = 0.f;
    }
    if (t == 0) { Rb[0][0] = -BIGF; Cb[0][1] = -BIGF; }  // R(0,1), C(1,0)
    float4 tC, tN, aC, aN;
    tN = *(const float4*)rowT;            // chunk 0 prefetch
    aN = *(const float4*)rowA;
    __syncthreads();

    int s = 0;
    for (int k = 2; k <= 512; k++) {
        const int jm1 = k - i - 1;        // 0-based column this thread touches
        const bool valid = (jm1 >= 0 && jm1 < MSEQ);
        if (valid) {
            const int sel = jm1 & 3;
            if (sel == 0) {
                tC = tN; aC = aN;
                if (jm1 + 4 < MSEQ) {
                    tN = *(const float4*)(rowT + jm1 + 4);
                    aN = *(const float4*)(rowA + jm1 + 4);
                }
            }
            float th = f4sel(tC, sel);
            float a  = f4sel(aC, sel);
            float u  = a + Rb[s][i - 1];                // c0 - c1
            float w  = a + Cb[s][i];                    // c2 - c1
            float m1 = fmaxf(fmaxf(u, w), 0.f);
            float L  = m1 + __logf(__expf(u - m1) + __expf(w - m1) +
                                   __expf(-m1));
            Rb[s ^ 1][i] = th + a + (L - w);
            Cb[s ^ 1][i] = th + a + (L - u);
            Wd[(size_t)k * 257 + i] = make_float2(u - L, w - L);
        }
        if (t == 0) Rb[s ^ 1][0] = 0.f;   // R(0,k), k>=2
        if (i == k) Cb[s ^ 1][i] = 0.f;   // C(k,0), k>=2 (k<=256 only)
        __syncthreads();
        s ^= 1;
    }

    // -------- backward --------
    float *Eb = Eb_, *E1 = E1_, *E2 = E2_;
    for (int m = t; m < 258; m += 256) {
        Eb[m] = (m == 256) ? 1.f : 0.f;   // E at (N,M) on diagonal k=512
        E1[m] = 0.f; E2[m] = 0.f;
        cu[m] = 0.f; cl[m] = 0.f; cd[m] = 0.f;
    }
    float4 alB = make_float4(0.f, 0.f, 0.f, 0.f);
    float2 cur = Wd[(size_t)512 * 257 + i];
    __syncthreads();

    for (int k = 512; k >= 2; k--) {
        float2 nxt;
        if (k > 2) nxt = Wd[(size_t)(k - 1) * 257 + i];   // one-step prefetch
        const int jm1 = k - i - 1;
        float E = Eb[i];
        float wu = 0.f, wl = 0.f, wd = 0.f;
        if (jm1 >= 0 && jm1 < MSEQ) {
            wu = E * __expf(cur.x);       // -> parent (i-1, j)
            wl = E * __expf(cur.y);       // -> parent (i,   j-1)
            wd = E - wu - wl;             // -> parent (i-1, j-1)
            const int sel = jm1 & 3;
            if      (sel == 3) alB.w = E;
            else if (sel == 2) alB.z = E;
            else if (sel == 1) alB.y = E;
            else               alB.x = E;
            if (sel == 0) *(float4*)(rowL + jm1) = alB;   // chunk complete
        }
        cu[i] = wu; cl[i] = wl; cd[i] = wd;
        __syncthreads();

        // accumulate into parent diagonals (slot m on diag k-1 gets up from
        // child i=m+1 and left from child i=m; diag k-2 slot m gets diag
        // contribution from child i=m+1)
        for (int m = t; m < 257; m += 256) {
            E1[m] += cu[m + 1] + cl[m];
            E2[m] += cd[m + 1];
        }
        for (int m = t; m < 258; m += 256) Eb[m] = 0.f;
        __syncthreads();

        float* tE = Eb; Eb = E1; E1 = E2; E2 = tE;
        cur = nxt;
    }
}

// ---------------------------------------------------------------------------
// Launch. Inputs: hx, hy, Wm, bm, Wg, bg (f32).
// Output: concat(aln, theta, A), each (64,256,256) f32.
// ---------------------------------------------------------------------------
extern "C" void kernel_launch(void* const* d_in, const int* in_sizes, int n_in,
                              void* d_out, int out_size)
{
    const float* hx = (const float*)d_in[0];
    const float* hy = (const float*)d_in[1];
    const float* Wm = (const float*)d_in[2];
    const float* bm = (const float*)d_in[3];
    const float* Wg = (const float*)d_in[4];
    const float* bg = (const float*)d_in[5];

    float* out = (float*)d_out;
    size_t third = (size_t)out_size / 3;       // 64*256*256
    float* aln_p   = out;
    float* theta_p = out + third;
    float* A_p     = out + 2 * third;

    k_proj<<<dim3(8, 256), 256>>>(hx, hy, Wm, bm, Wg, bg);
    k_pair<<<dim3(2, 2, 2 * BATCH), 256>>>(theta_p, A_p);
    k_nw<<<BATCH, 256>>>(theta_p, A_p, aln_p);
}